// round 1
// baseline (speedup 1.0000x reference)
#include <cuda_runtime.h>
#include <math.h>

// ---------------------------------------------------------------------------
// Problem constants (GPT-J block)
// ---------------------------------------------------------------------------
#define B_      2
#define S_      2048
#define E_      4096
#define H_      16
#define D_      256
#define INNER_  16384
#define BH_     (B_ * H_)
#define TOK_    (B_ * S_)          // 4096 tokens

// ---------------------------------------------------------------------------
// Device scratch (static __device__ globals — allocation-free per harness rules)
// ---------------------------------------------------------------------------
static __device__ float g_h    [(size_t)TOK_ * E_];         // LN output        64 MB
static __device__ float g_qlin [(size_t)TOK_ * E_];         // q before rope    64 MB
static __device__ float g_klin [(size_t)TOK_ * E_];         // k before rope    64 MB
static __device__ float g_vlin [(size_t)TOK_ * E_];         // v                64 MB
static __device__ float g_q    [(size_t)BH_ * S_ * D_];     // (b,h,s,d)        64 MB
static __device__ float g_kc   [(size_t)BH_ * S_ * D_];     // key cache (b,h,t,d)
static __device__ float g_vc   [(size_t)BH_ * S_ * D_];     // value cache
static __device__ float g_scores[(size_t)BH_ * S_ * S_];    // attn scores      537 MB
static __device__ float g_ctx  [(size_t)TOK_ * E_];         // attn context (B,S,E)
static __device__ float g_act  [(size_t)TOK_ * INNER_];     // MLP activation   268 MB

// ---------------------------------------------------------------------------
// Small helpers
// ---------------------------------------------------------------------------
__device__ __forceinline__ float gelu_tanh(float x) {
    float x3 = x * x * x;
    float u  = 0.7978845608028654f * (x + 0.044715f * x3);
    return 0.5f * x * (1.0f + tanhf(u));
}

// ---------------------------------------------------------------------------
// LayerNorm: one block per token
// ---------------------------------------------------------------------------
__global__ void ln_kernel(const float* __restrict__ x,
                          const float* __restrict__ g,
                          const float* __restrict__ b,
                          float* __restrict__ h) {
    int row = blockIdx.x;
    int t   = threadIdx.x;
    const float* xr = x + (size_t)row * E_;
    float s = 0.f, sq = 0.f;
    for (int i = t; i < E_; i += 256) {
        float v = xr[i];
        s += v; sq += v * v;
    }
    __shared__ float rs[256], rq[256];
    rs[t] = s; rq[t] = sq;
    __syncthreads();
    for (int st = 128; st > 0; st >>= 1) {
        if (t < st) { rs[t] += rs[t + st]; rq[t] += rq[t + st]; }
        __syncthreads();
    }
    float mu  = rs[0] * (1.f / E_);
    float var = rq[0] * (1.f / E_) - mu * mu;
    float inv = rsqrtf(var + 1e-5f);
    float* hr = h + (size_t)row * E_;
    for (int i = t; i < E_; i += 256)
        hr[i] = (xr[i] - mu) * inv * g[i] + b[i];
}

// ---------------------------------------------------------------------------
// Cache init: (B, BUCKET, H, D) -> (B, H, BUCKET, D)
// ---------------------------------------------------------------------------
__global__ void cache_init_kernel(const float* __restrict__ pk,
                                  const float* __restrict__ pv,
                                  float* __restrict__ kc,
                                  float* __restrict__ vc) {
    size_t i = (size_t)blockIdx.x * blockDim.x + threadIdx.x;
    const size_t total = (size_t)B_ * S_ * H_ * D_;
    if (i >= total) return;
    int d  = (int)(i & (D_ - 1));
    int h  = (int)((i >> 8) & (H_ - 1));
    int tt = (int)((i >> 12) & (S_ - 1));
    int b  = (int)(i >> 23);
    size_t dst = (((size_t)(b * H_ + h) * S_) + tt) * D_ + d;
    kc[dst] = pk[i];
    vc[dst] = pv[i];
}

// ---------------------------------------------------------------------------
// RoPE + transpose q to (b,h,s,d), scatter k,v into caches
// grid = B*S*H blocks, 128 threads (2 dims per thread)
// ---------------------------------------------------------------------------
__global__ void rope_scatter_kernel(const float* __restrict__ ql,
                                    const float* __restrict__ kl,
                                    const float* __restrict__ vl,
                                    const int* __restrict__ kloc,
                                    const int* __restrict__ vloc,
                                    const int* __restrict__ pos,
                                    float* __restrict__ qo,
                                    float* __restrict__ kc,
                                    float* __restrict__ vc) {
    int bsh = blockIdx.x;
    int h   = bsh & (H_ - 1);
    int bs  = bsh >> 4;            // b*S + s
    int s   = bs & (S_ - 1);
    int b   = bs >> 11;
    int t   = threadIdx.x;         // 0..127
    int d0  = 2 * t;

    size_t src = ((size_t)bs * H_ + h) * D_;
    int p  = pos[bs];
    int lk = kloc[bs];
    int lv = vloc[bs];

    size_t qdst = (((size_t)(b * H_ + h) * S_) + s)  * D_;
    size_t kdst = (((size_t)(b * H_ + h) * S_) + lk) * D_;
    size_t vdst = (((size_t)(b * H_ + h) * S_) + lv) * D_;

    float q0 = ql[src + d0], q1 = ql[src + d0 + 1];
    float k0 = kl[src + d0], k1 = kl[src + d0 + 1];

    if (t < 32) {   // rotary on first 64 dims
        float invf = powf(10000.f, -(float)d0 / 64.f);
        float ang  = (float)p * invf;
        float sn, cs;
        sincosf(ang, &sn, &cs);
        float nq0 = q0 * cs - q1 * sn, nq1 = q1 * cs + q0 * sn;
        float nk0 = k0 * cs - k1 * sn, nk1 = k1 * cs + k0 * sn;
        q0 = nq0; q1 = nq1; k0 = nk0; k1 = nk1;
    }
    qo[qdst + d0] = q0; qo[qdst + d0 + 1] = q1;
    kc[kdst + d0] = k0; kc[kdst + d0 + 1] = k1;
    vc[vdst + d0] = vl[src + d0];
    vc[vdst + d0 + 1] = vl[src + d0 + 1];
}

// ---------------------------------------------------------------------------
// Masked causal softmax over score rows. grid = BH*S blocks, 256 threads.
// Writes p for k<=s and 0 for s<k<kcap (kcap = next 128 boundary), matching
// the K-range the AV GEMM reads.
// ---------------------------------------------------------------------------
__global__ void softmax_kernel(float* __restrict__ sc) {
    size_t row = blockIdx.x;                 // bh*S + s
    int s = (int)(row & (S_ - 1));
    float* p = sc + row * S_;
    int kcap = ((s >> 7) + 1) << 7;
    int t = threadIdx.x;

    float vals[8];
    float vmax = -3.0e38f;
    int nIter = (kcap + 255) >> 8;
    for (int i = 0; i < nIter; i++) {
        int k = i * 256 + t;
        float v = -3.0e38f;
        if (k <= s) v = p[k];
        vals[i] = v;
        vmax = fmaxf(vmax, v);
    }
    __shared__ float red[256];
    red[t] = vmax; __syncthreads();
    for (int st = 128; st > 0; st >>= 1) {
        if (t < st) red[t] = fmaxf(red[t], red[t + st]);
        __syncthreads();
    }
    vmax = red[0];
    __syncthreads();

    float sum = 0.f;
    for (int i = 0; i < nIter; i++) {
        int k = i * 256 + t;
        float e = 0.f;
        if (k <= s) e = __expf((vals[i] - vmax) * 0.0625f);  // /sqrt(256)
        vals[i] = e;
        sum += e;
    }
    red[t] = sum; __syncthreads();
    for (int st = 128; st > 0; st >>= 1) {
        if (t < st) red[t] += red[t + st];
        __syncthreads();
    }
    float inv = 1.f / red[0];
    for (int i = 0; i < nIter; i++) {
        int k = i * 256 + t;
        if (k < kcap) p[k] = vals[i] * inv;
    }
}

// ---------------------------------------------------------------------------
// Generic fp32 SGEMM, 128x128 tile, Ksteps of 8, 256 threads, 8x8 microtile.
//   C[m,n] = sum_k A[m,k] * (TRANSB ? B[n,k] : B[k,n])   (+ epilogue)
// Batch offsets: off = (z / hdiv) * so + (z % hdiv) * si
// EPI: 0 = store, 1 = gelu(acc + bias[n]), 2 = acc + res[m,n], 3 = C += acc + bias[n]
// CSKIP: skip blocks fully above the causal diagonal (scores GEMM)
// CKLIM: clamp K loop to m0+128 (AV GEMM; rows only attend to k<=s)
// Requires M,N % 128 == 0, K % 8 == 0, 16B-aligned pointers/strides.
// ---------------------------------------------------------------------------
template<bool TRANSB, int EPI, bool CSKIP, bool CKLIM>
__global__ __launch_bounds__(256)
void sgemm_kernel(const float* __restrict__ Ag, const float* __restrict__ Bg,
                  float* __restrict__ Cg,
                  int M, int N, int K,
                  int lda, int ldb, int ldc,
                  long aso, long asi, int ahdiv,
                  long bso, long bsi, int bhdiv,
                  long cso, long csi, int chdiv,
                  const float* __restrict__ bias,
                  const float* __restrict__ res) {
    int z = blockIdx.z;
    const float* A = Ag + (z / ahdiv) * aso + (z % ahdiv) * asi;
    const float* B = Bg + (z / bhdiv) * bso + (z % bhdiv) * bsi;
    float*       C = Cg + (z / chdiv) * cso + (z % chdiv) * csi;

    int m0 = blockIdx.y * 128;
    int n0 = blockIdx.x * 128;
    if (CSKIP && n0 > m0 + 127) return;
    int kEnd = CKLIM ? min(K, m0 + 128) : K;

    __shared__ float As[8][128];
    __shared__ float Bs[8][128];

    int tid = threadIdx.x;
    int tx = tid & 15, ty = tid >> 4;

    // A-tile load mapping (transpose into As[k][m])
    int arow  = tid >> 1;          // 0..127
    int acol4 = (tid & 1) * 4;     // 0 or 4
    // B-tile NN load mapping
    int brow  = tid >> 5;          // 0..7
    int bcol4 = (tid & 31) * 4;    // 0..124

    float c[8][8];
    #pragma unroll
    for (int i = 0; i < 8; i++)
        #pragma unroll
        for (int j = 0; j < 8; j++) c[i][j] = 0.f;

    for (int k0 = 0; k0 < kEnd; k0 += 8) {
        float4 av = *(const float4*)(A + (size_t)(m0 + arow) * lda + k0 + acol4);
        float4 bv;
        if (TRANSB)
            bv = *(const float4*)(B + (size_t)(n0 + arow) * ldb + k0 + acol4);
        else
            bv = *(const float4*)(B + (size_t)(k0 + brow) * ldb + n0 + bcol4);

        __syncthreads();
        As[acol4 + 0][arow] = av.x;
        As[acol4 + 1][arow] = av.y;
        As[acol4 + 2][arow] = av.z;
        As[acol4 + 3][arow] = av.w;
        if (TRANSB) {
            Bs[acol4 + 0][arow] = bv.x;
            Bs[acol4 + 1][arow] = bv.y;
            Bs[acol4 + 2][arow] = bv.z;
            Bs[acol4 + 3][arow] = bv.w;
        } else {
            *(float4*)&Bs[brow][bcol4] = bv;
        }
        __syncthreads();

        #pragma unroll
        for (int k = 0; k < 8; k++) {
            float4 a0 = *(const float4*)&As[k][ty * 4];
            float4 a1 = *(const float4*)&As[k][64 + ty * 4];
            float4 b0 = *(const float4*)&Bs[k][tx * 4];
            float4 b1 = *(const float4*)&Bs[k][64 + tx * 4];
            float a[8] = {a0.x, a0.y, a0.z, a0.w, a1.x, a1.y, a1.z, a1.w};
            float b[8] = {b0.x, b0.y, b0.z, b0.w, b1.x, b1.y, b1.z, b1.w};
            #pragma unroll
            for (int i = 0; i < 8; i++)
                #pragma unroll
                for (int j = 0; j < 8; j++)
                    c[i][j] += a[i] * b[j];
        }
    }

    // Epilogue
    #pragma unroll
    for (int i = 0; i < 8; i++) {
        int grow = m0 + ((i < 4) ? (ty * 4 + i) : (64 + ty * 4 + i - 4));
        #pragma unroll
        for (int jj = 0; jj < 2; jj++) {
            int cbase = (jj == 0) ? (tx * 4) : (64 + tx * 4);
            size_t off = (size_t)grow * ldc + n0 + cbase;
            float4 v = make_float4(c[i][jj * 4 + 0], c[i][jj * 4 + 1],
                                   c[i][jj * 4 + 2], c[i][jj * 4 + 3]);
            if (EPI == 1) {
                v.x = gelu_tanh(v.x + bias[n0 + cbase + 0]);
                v.y = gelu_tanh(v.y + bias[n0 + cbase + 1]);
                v.z = gelu_tanh(v.z + bias[n0 + cbase + 2]);
                v.w = gelu_tanh(v.w + bias[n0 + cbase + 3]);
            } else if (EPI == 2) {
                float4 r = *(const float4*)(res + off);
                v.x += r.x; v.y += r.y; v.z += r.z; v.w += r.w;
            } else if (EPI == 3) {
                float4 o = *(const float4*)(C + off);
                v.x = o.x + v.x + bias[n0 + cbase + 0];
                v.y = o.y + v.y + bias[n0 + cbase + 1];
                v.z = o.z + v.z + bias[n0 + cbase + 2];
                v.w = o.w + v.w + bias[n0 + cbase + 3];
            }
            *(float4*)(C + off) = v;
        }
    }
}

// ---------------------------------------------------------------------------
// Host launcher
// ---------------------------------------------------------------------------
extern "C" void kernel_launch(void* const* d_in, const int* in_sizes, int n_in,
                              void* d_out, int out_size) {
    (void)in_sizes; (void)n_in; (void)out_size;
    const float* hidden   = (const float*)d_in[0];
    const float* ln_g     = (const float*)d_in[1];
    const float* ln_b     = (const float*)d_in[2];
    const float* wq       = (const float*)d_in[3];
    const float* wk       = (const float*)d_in[4];
    const float* wv       = (const float*)d_in[5];
    const float* wo       = (const float*)d_in[6];
    const float* fc_in_w  = (const float*)d_in[7];
    const float* fc_in_b  = (const float*)d_in[8];
    const float* fc_out_w = (const float*)d_in[9];
    const float* fc_out_b = (const float*)d_in[10];
    const float* past_k   = (const float*)d_in[11];
    const float* past_v   = (const float*)d_in[12];
    const int*   kloc     = (const int*)d_in[13];
    const int*   vloc     = (const int*)d_in[14];
    const int*   pos      = (const int*)d_in[15];
    float* out = (float*)d_out;

    float *h, *qlin, *klin, *vlin, *q, *kc, *vc, *scores, *ctx, *act;
    cudaGetSymbolAddress((void**)&h,      g_h);
    cudaGetSymbolAddress((void**)&qlin,   g_qlin);
    cudaGetSymbolAddress((void**)&klin,   g_klin);
    cudaGetSymbolAddress((void**)&vlin,   g_vlin);
    cudaGetSymbolAddress((void**)&q,      g_q);
    cudaGetSymbolAddress((void**)&kc,     g_kc);
    cudaGetSymbolAddress((void**)&vc,     g_vc);
    cudaGetSymbolAddress((void**)&scores, g_scores);
    cudaGetSymbolAddress((void**)&ctx,    g_ctx);
    cudaGetSymbolAddress((void**)&act,    g_act);

    // 1) LayerNorm
    ln_kernel<<<TOK_, 256>>>(hidden, ln_g, ln_b, h);

    // 2) QKV projections (NN, plain)
    dim3 g44(E_ / 128, TOK_ / 128, 1);
    sgemm_kernel<false, 0, false, false><<<g44, 256>>>(
        h, wq, qlin, TOK_, E_, E_, E_, E_, E_,
        0, 0, 1, 0, 0, 1, 0, 0, 1, nullptr, nullptr);
    sgemm_kernel<false, 0, false, false><<<g44, 256>>>(
        h, wk, klin, TOK_, E_, E_, E_, E_, E_,
        0, 0, 1, 0, 0, 1, 0, 0, 1, nullptr, nullptr);
    sgemm_kernel<false, 0, false, false><<<g44, 256>>>(
        h, wv, vlin, TOK_, E_, E_, E_, E_, E_,
        0, 0, 1, 0, 0, 1, 0, 0, 1, nullptr, nullptr);

    // 3) Init caches from past, then RoPE + scatter
    {
        size_t total = (size_t)B_ * S_ * H_ * D_;
        cache_init_kernel<<<(unsigned)((total + 255) / 256), 256>>>(past_k, past_v, kc, vc);
    }
    rope_scatter_kernel<<<B_ * S_ * H_, 128>>>(qlin, klin, vlin, kloc, vloc, pos, q, kc, vc);

    // 4) Attention scores (batched NT, causal block skip)
    dim3 gs(S_ / 128, S_ / 128, BH_);
    sgemm_kernel<true, 0, true, false><<<gs, 256>>>(
        q, kc, scores, S_, S_, D_, D_, D_, S_,
        (long)S_ * D_, 0, 1,
        (long)S_ * D_, 0, 1,
        (long)S_ * S_, 0, 1, nullptr, nullptr);

    // 5) Softmax with causal mask
    softmax_kernel<<<BH_ * S_, 256>>>(scores);

    // 6) Attention * V (batched NN, K clamped causally), write (B,S,E)
    dim3 gav(D_ / 128, S_ / 128, BH_);
    sgemm_kernel<false, 0, false, true><<<gav, 256>>>(
        scores, vc, ctx, S_, D_, S_, S_, D_, E_,
        (long)S_ * S_, 0, 1,
        (long)S_ * D_, 0, 1,
        (long)S_ * E_, (long)D_, H_, nullptr, nullptr);

    // 7) O projection + residual (out = ctx@wo + hidden)
    sgemm_kernel<false, 2, false, false><<<g44, 256>>>(
        ctx, wo, out, TOK_, E_, E_, E_, E_, E_,
        0, 0, 1, 0, 0, 1, 0, 0, 1, nullptr, hidden);

    // 8) MLP fc_in + bias + gelu
    dim3 gfi(INNER_ / 128, TOK_ / 128, 1);
    sgemm_kernel<false, 1, false, false><<<gfi, 256>>>(
        h, fc_in_w, act, TOK_, INNER_, E_, E_, INNER_, INNER_,
        0, 0, 1, 0, 0, 1, 0, 0, 1, fc_in_b, nullptr);

    // 9) MLP fc_out + bias, accumulate into out
    sgemm_kernel<false, 3, false, false><<<g44, 256>>>(
        act, fc_out_w, out, TOK_, E_, INNER_, INNER_, E_, E_,
        0, 0, 1, 0, 0, 1, 0, 0, 1, fc_out_b, nullptr);
}

// round 3
// speedup vs baseline: 1.6345x; 1.6345x over previous
#include <cuda_runtime.h>
#include <math.h>
#include <stdint.h>

// ---------------------------------------------------------------------------
// Problem constants (GPT-J block)
// ---------------------------------------------------------------------------
#define B_      2
#define S_      2048
#define E_      4096
#define H_      16
#define D_      256
#define INNER_  16384
#define BH_     (B_ * H_)
#define TOK_    (B_ * S_)          // 4096 tokens

// Arch-feature gate: tcgen05 only exists on sm_103a ("all-features") builds.
#if defined(__CUDA_ARCH__) && defined(__CUDA_ARCH_FEAT_SM103_ALL)
#define USE_TCGEN05 1
#else
#define USE_TCGEN05 0
#endif

// ---------------------------------------------------------------------------
// Device scratch (static __device__ globals — allocation-free per harness rules)
// ---------------------------------------------------------------------------
static __device__ float g_h    [(size_t)TOK_ * E_];
static __device__ float g_qlin [(size_t)TOK_ * E_];
static __device__ float g_klin [(size_t)TOK_ * E_];
static __device__ float g_vlin [(size_t)TOK_ * E_];
static __device__ float g_q    [(size_t)BH_ * S_ * D_];     // (b,h,s,d)
static __device__ float g_kc   [(size_t)BH_ * S_ * D_];     // key cache (b,h,t,d)
static __device__ float g_vcT  [(size_t)BH_ * D_ * S_];     // value cache transposed (b,h,d,t)
static __device__ float g_scores[(size_t)BH_ * S_ * S_];
static __device__ float g_ctx  [(size_t)TOK_ * E_];
static __device__ float g_act  [(size_t)TOK_ * INNER_];
static __device__ float g_wqT  [(size_t)E_ * E_];
static __device__ float g_wkT  [(size_t)E_ * E_];
static __device__ float g_wvT  [(size_t)E_ * E_];
static __device__ float g_woT  [(size_t)E_ * E_];
static __device__ float g_fiT  [(size_t)E_ * INNER_];
static __device__ float g_foT  [(size_t)INNER_ * E_];

// ---------------------------------------------------------------------------
// Common helpers
// ---------------------------------------------------------------------------
__device__ __forceinline__ uint32_t smem_u32(const void* p) {
    uint32_t a;
    asm("{ .reg .u64 t; cvta.to.shared.u64 t, %1; cvt.u32.u64 %0, t; }" : "=r"(a) : "l"(p));
    return a;
}
__device__ __forceinline__ float gelu_tanh(float x) {
    float x3 = x * x * x;
    float u  = 0.7978845608028654f * (x + 0.044715f * x3);
    return 0.5f * x * (1.0f + tanhf(u));
}

// -------------------- tcgen05 helpers (only referenced on sm_103a) ---------
__device__ __forceinline__ bool elect_one() {
    uint32_t pred;
    asm volatile("{\n\t.reg .pred p;\n\telect.sync _|p, 0xFFFFFFFF;\n\tselp.b32 %0, 1, 0, p;\n\t}" : "=r"(pred));
    return pred != 0;
}
__device__ __forceinline__ void tc_alloc(uint32_t smem_res, uint32_t ncols) {
    asm volatile("tcgen05.alloc.cta_group::1.sync.aligned.shared::cta.b32 [%0], %1;"
                 :: "r"(smem_res), "r"(ncols) : "memory");
}
__device__ __forceinline__ void tc_dealloc(uint32_t tmem, uint32_t ncols) {
    asm volatile("tcgen05.dealloc.cta_group::1.sync.aligned.b32 %0, %1;" :: "r"(tmem), "r"(ncols));
}
__device__ __forceinline__ void tc_relinq() {
    asm volatile("tcgen05.relinquish_alloc_permit.cta_group::1.sync.aligned;");
}
__device__ __forceinline__ void tc_commit(uint32_t mbar) {
    asm volatile("tcgen05.commit.cta_group::1.mbarrier::arrive::one.shared::cluster.b64 [%0];"
                 :: "r"(mbar) : "memory");
}
__device__ __forceinline__ void tc_fence_after() {
    asm volatile("tcgen05.fence::after_thread_sync;" ::: "memory");
}
__device__ __forceinline__ void tc_fence_before() {
    asm volatile("tcgen05.fence::before_thread_sync;" ::: "memory");
}
__device__ __forceinline__ void tc_wait_ld() {
    asm volatile("tcgen05.wait::ld.sync.aligned;" ::: "memory");
}
__device__ __forceinline__ void fence_proxy_async_cta() {
    asm volatile("fence.proxy.async.shared::cta;" ::: "memory");
}
__device__ __forceinline__ void mbar_init(uint32_t mbar, uint32_t cnt) {
    asm volatile("mbarrier.init.shared.b64 [%0], %1;" :: "r"(mbar), "r"(cnt) : "memory");
}
__device__ __forceinline__ void mbar_wait(uint32_t mbar, uint32_t parity) {
    asm volatile("{\n\t.reg .pred P;\n\t"
                 "WL%=:\n\t"
                 "mbarrier.try_wait.parity.acquire.cta.shared::cta.b64 P, [%0], %1, 0x989680;\n\t"
                 "@!P bra WL%=;\n\t}"
                 :: "r"(mbar), "r"(parity) : "memory");
}
__device__ __forceinline__ void tc_mma_tf32(uint32_t d, uint64_t ad, uint64_t bd,
                                            uint32_t idesc, bool acc) {
    uint32_t e = acc ? 1u : 0u;
    asm volatile("{\n\t.reg .pred p;\n\t"
                 "setp.ne.u32 p, %4, 0;\n\t"
                 "tcgen05.mma.cta_group::1.kind::tf32 [%0], %1, %2, %3, {%5, %5, %5, %5}, p;\n\t}"
                 :: "r"(d), "l"(ad), "l"(bd), "r"(idesc), "r"(e), "r"(0u) : "memory");
}
#define LDTM_X32(r, addr) \
    asm volatile("tcgen05.ld.sync.aligned.32x32b.x32.b32 " \
        "{%0,%1,%2,%3,%4,%5,%6,%7,%8,%9,%10,%11,%12,%13,%14,%15," \
        "%16,%17,%18,%19,%20,%21,%22,%23,%24,%25,%26,%27,%28,%29,%30,%31}, [%32];" \
        : "=r"((r)[0]),"=r"((r)[1]),"=r"((r)[2]),"=r"((r)[3]), \
          "=r"((r)[4]),"=r"((r)[5]),"=r"((r)[6]),"=r"((r)[7]), \
          "=r"((r)[8]),"=r"((r)[9]),"=r"((r)[10]),"=r"((r)[11]), \
          "=r"((r)[12]),"=r"((r)[13]),"=r"((r)[14]),"=r"((r)[15]), \
          "=r"((r)[16]),"=r"((r)[17]),"=r"((r)[18]),"=r"((r)[19]), \
          "=r"((r)[20]),"=r"((r)[21]),"=r"((r)[22]),"=r"((r)[23]), \
          "=r"((r)[24]),"=r"((r)[25]),"=r"((r)[26]),"=r"((r)[27]), \
          "=r"((r)[28]),"=r"((r)[29]),"=r"((r)[30]),"=r"((r)[31]) \
        : "r"(addr))

static constexpr uint64_t DESC_BASE_SW128 =
    (uint64_t(2) << 61) | (uint64_t(1) << 46) | (uint64_t(64) << 32) | (uint64_t(1) << 16);
__device__ __forceinline__ uint64_t mkdesc(uint32_t addr) {
    return DESC_BASE_SW128 | ((uint64_t)(addr >> 4) & 0x3FFF);
}
__device__ __forceinline__ uint32_t sw128(uint32_t off) { return off ^ ((off >> 3) & 0x70); }

__device__ __forceinline__ void hilo_sts(uint32_t hiaddr, uint32_t loaddr, float4 v) {
    uint32_t hx = __float_as_uint(v.x) & 0xFFFFE000u;
    uint32_t hy = __float_as_uint(v.y) & 0xFFFFE000u;
    uint32_t hz = __float_as_uint(v.z) & 0xFFFFE000u;
    uint32_t hw = __float_as_uint(v.w) & 0xFFFFE000u;
    float lx = v.x - __uint_as_float(hx);
    float ly = v.y - __uint_as_float(hy);
    float lz = v.z - __uint_as_float(hz);
    float lw = v.w - __uint_as_float(hw);
    asm volatile("st.shared.v4.b32 [%0], {%1,%2,%3,%4};"
                 :: "r"(hiaddr), "r"(hx), "r"(hy), "r"(hz), "r"(hw) : "memory");
    asm volatile("st.shared.v4.b32 [%0], {%1,%2,%3,%4};"
                 :: "r"(loaddr), "r"(__float_as_uint(lx)), "r"(__float_as_uint(ly)),
                    "r"(__float_as_uint(lz)), "r"(__float_as_uint(lw)) : "memory");
}

// -------------------- mma.sync fallback helpers (plain sm_103) -------------
__device__ __forceinline__ void cpa16(uint32_t dst, const void* src) {
    asm volatile("cp.async.cg.shared.global [%0], [%1], 16;" :: "r"(dst), "l"(src));
}
__device__ __forceinline__ void cpa_commit() {
    asm volatile("cp.async.commit_group;" ::: "memory");
}
template<int N>
__device__ __forceinline__ void cpa_wait() {
    asm volatile("cp.async.wait_group %0;" :: "n"(N) : "memory");
}
__device__ __forceinline__ void split_tf32(float v, uint32_t& hi, uint32_t& lo) {
    asm("cvt.rna.tf32.f32 %0, %1;" : "=r"(hi) : "f"(v));
    float l = v - __uint_as_float(hi);
    asm("cvt.rna.tf32.f32 %0, %1;" : "=r"(lo) : "f"(l));
}
#define MMA_TF32(c, A0, A1, A2, A3, B0, B1) \
    asm volatile("mma.sync.aligned.m16n8k8.row.col.f32.tf32.tf32.f32 " \
        "{%0,%1,%2,%3}, {%4,%5,%6,%7}, {%8,%9}, {%0,%1,%2,%3};" \
        : "+f"((c)[0]), "+f"((c)[1]), "+f"((c)[2]), "+f"((c)[3]) \
        : "r"(A0), "r"(A1), "r"(A2), "r"(A3), "r"(B0), "r"(B1))

// ---------------------------------------------------------------------------
// Elementwise kernels
// ---------------------------------------------------------------------------
__global__ void ln_kernel(const float* __restrict__ x, const float* __restrict__ g,
                          const float* __restrict__ b, float* __restrict__ h) {
    int row = blockIdx.x;
    int t   = threadIdx.x;
    const float* xr = x + (size_t)row * E_;
    float s = 0.f, sq = 0.f;
    for (int i = t; i < E_; i += 256) { float v = xr[i]; s += v; sq += v * v; }
    __shared__ float rs[256], rq[256];
    rs[t] = s; rq[t] = sq;
    __syncthreads();
    for (int st = 128; st > 0; st >>= 1) {
        if (t < st) { rs[t] += rs[t + st]; rq[t] += rq[t + st]; }
        __syncthreads();
    }
    float mu  = rs[0] * (1.f / E_);
    float var = rq[0] * (1.f / E_) - mu * mu;
    float inv = rsqrtf(var + 1e-5f);
    float* hr = h + (size_t)row * E_;
    for (int i = t; i < E_; i += 256)
        hr[i] = (xr[i] - mu) * inv * g[i] + b[i];
}

__global__ void cache_init_kernel(const float* __restrict__ pk, const float* __restrict__ pv,
                                  float* __restrict__ kc, float* __restrict__ vcT) {
    size_t i = (size_t)blockIdx.x * blockDim.x + threadIdx.x;
    const size_t total = (size_t)B_ * S_ * H_ * D_;
    if (i >= total) return;
    int d  = (int)(i & (D_ - 1));
    int h  = (int)((i >> 8) & (H_ - 1));
    int tt = (int)((i >> 12) & (S_ - 1));
    int b  = (int)(i >> 23);
    kc [(((size_t)(b * H_ + h) * S_) + tt) * D_ + d] = pk[i];
    vcT[(((size_t)(b * H_ + h) * D_) + d) * S_ + tt] = pv[i];
}

__global__ void rope_scatter_kernel(const float* __restrict__ ql, const float* __restrict__ kl,
                                    const float* __restrict__ vl,
                                    const int* __restrict__ kloc, const int* __restrict__ vloc,
                                    const int* __restrict__ pos,
                                    float* __restrict__ qo, float* __restrict__ kc,
                                    float* __restrict__ vcT) {
    int bsh = blockIdx.x;
    int h   = bsh & (H_ - 1);
    int bs  = bsh >> 4;
    int s   = bs & (S_ - 1);
    int b   = bs >> 11;
    int t   = threadIdx.x;
    int d0  = 2 * t;

    size_t src = ((size_t)bs * H_ + h) * D_;
    int p  = pos[bs];
    int lk = kloc[bs];
    int lv = vloc[bs];

    size_t qdst = (((size_t)(b * H_ + h) * S_) + s)  * D_;
    size_t kdst = (((size_t)(b * H_ + h) * S_) + lk) * D_;
    size_t vbase = ((size_t)(b * H_ + h) * D_) * S_;

    float q0 = ql[src + d0], q1 = ql[src + d0 + 1];
    float k0 = kl[src + d0], k1 = kl[src + d0 + 1];

    if (t < 32) {
        float invf = powf(10000.f, -(float)d0 / 64.f);
        float ang  = (float)p * invf;
        float sn, cs;
        sincosf(ang, &sn, &cs);
        float nq0 = q0 * cs - q1 * sn, nq1 = q1 * cs + q0 * sn;
        float nk0 = k0 * cs - k1 * sn, nk1 = k1 * cs + k0 * sn;
        q0 = nq0; q1 = nq1; k0 = nk0; k1 = nk1;
    }
    qo[qdst + d0] = q0; qo[qdst + d0 + 1] = q1;
    kc[kdst + d0] = k0; kc[kdst + d0 + 1] = k1;
    vcT[vbase + (size_t)d0 * S_ + lv]       = vl[src + d0];
    vcT[vbase + (size_t)(d0 + 1) * S_ + lv] = vl[src + d0 + 1];
}

__global__ void softmax_kernel(float* __restrict__ sc) {
    size_t row = blockIdx.x;
    int s = (int)(row & (S_ - 1));
    float* p = sc + row * (size_t)S_;
    int kcap = ((s >> 7) + 1) << 7;
    int t = threadIdx.x;

    float vals[8];
    float vmax = -3.0e38f;
    int nIter = (kcap + 255) >> 8;
    for (int i = 0; i < nIter; i++) {
        int k = i * 256 + t;
        float v = -3.0e38f;
        if (k <= s) v = p[k];
        vals[i] = v;
        vmax = fmaxf(vmax, v);
    }
    __shared__ float red[256];
    red[t] = vmax; __syncthreads();
    for (int st = 128; st > 0; st >>= 1) {
        if (t < st) red[t] = fmaxf(red[t], red[t + st]);
        __syncthreads();
    }
    vmax = red[0];
    __syncthreads();

    float sum = 0.f;
    for (int i = 0; i < nIter; i++) {
        int k = i * 256 + t;
        float e = 0.f;
        if (k <= s) e = __expf((vals[i] - vmax) * 0.0625f);
        vals[i] = e;
        sum += e;
    }
    red[t] = sum; __syncthreads();
    for (int st = 128; st > 0; st >>= 1) {
        if (t < st) red[t] += red[t + st];
        __syncthreads();
    }
    float inv = 1.f / red[0];
    for (int i = 0; i < nIter; i++) {
        int k = i * 256 + t;
        if (k < kcap) p[k] = vals[i] * inv;
    }
}

// in[K][N] row-major -> out[N][K]
__global__ void transpose_kernel(const float* __restrict__ in, float* __restrict__ out,
                                 int K, int N) {
    __shared__ float tile[32][33];
    int nb = blockIdx.x * 32, kb = blockIdx.y * 32;
    int tx = threadIdx.x, ty = threadIdx.y;
    #pragma unroll
    for (int i = 0; i < 4; i++)
        tile[ty + 8 * i][tx] = in[(size_t)(kb + ty + 8 * i) * N + nb + tx];
    __syncthreads();
    #pragma unroll
    for (int i = 0; i < 4; i++)
        out[(size_t)(nb + ty + 8 * i) * K + kb + tx] = tile[tx][ty + 8 * i];
}

// ---------------------------------------------------------------------------
// GEMM:  C[M,N](+)= A[M,K] * B[N,K]^T  (both K-major fp32), 3xTF32 precision.
// CTA tile 128x128.  Two implementations selected by arch feature:
//   sm_103a : tcgen05 SS-mode, TMEM accumulator, double-buffered SMEM
//   sm_103  : mma.sync.m16n8k8 tf32, cp.async 4-stage pipeline
// EPI: 0 store | 1 gelu(acc+bias) | 2 acc+res | 3 C += acc+bias
// CSKIP: skip blocks fully above causal diagonal. CKLIM: kEnd = m0+128.
// ---------------------------------------------------------------------------
#define TC_STAGE   65536u   // Ahi 16K + Alo 16K + Bhi 16K + Blo 16K
#define SMEMB      (1024u + 2u * TC_STAGE)   // 132 KB, used by both paths
#define TC_OFF_AL  16384u
#define TC_OFF_BH  32768u
#define TC_OFF_BL  49152u

static constexpr uint32_t IDESC_TF32 =
    (1u << 4) | (2u << 7) | (2u << 10) | ((128u / 8u) << 17) | ((128u / 16u) << 24);

template<int EPI, bool CSKIP, bool CKLIM>
__global__ __launch_bounds__(256, 1)
void tc_gemm(const float* __restrict__ Ag, const float* __restrict__ Bg,
             float* __restrict__ Cg,
             int K, int ldc,
             long long aso, long long bso, long long cso, long long csi, int chdiv,
             const float* __restrict__ bias, const float* __restrict__ res) {
    int m0 = blockIdx.y * 128;
    int n0 = blockIdx.x * 128;
    if (CSKIP && n0 > m0 + 127) return;
    int z = blockIdx.z;
    const float* A = Ag + (size_t)z * aso;
    const float* B = Bg + (size_t)z * bso;
    float*       C = Cg + (size_t)(z / chdiv) * cso + (size_t)(z % chdiv) * csi;

    int kEnd = CKLIM ? min(K, m0 + 128) : K;

    extern __shared__ char smem[];
    int tid = threadIdx.x;

#if USE_TCGEN05
    // =======================  tcgen05 path (sm_103a)  =======================
    int nch = kEnd >> 5;                     // K-chunks of 32
    uint32_t sb  = smem_u32(smem);
    uint32_t MB0 = sb + 8, MB1 = sb + 16;
    int wid = tid >> 5;

    if (wid == 0) tc_alloc(sb, 128);
    if (tid == 0) { mbar_init(MB0, 1); mbar_init(MB1, 1); }
    __syncthreads();
    uint32_t tmem;
    asm volatile("ld.shared.b32 %0, [%1];" : "=r"(tmem) : "r"(sb));

    const uint32_t T0 = sb + 1024;

    int am = tid & 127, aq = (tid >> 7) * 4;            // 2 threads/row, 4 quads
    const float* asrc = A + (size_t)(m0 + am) * K + aq * 4;
    const float* bsrc = B + (size_t)(n0 + am) * K + aq * 4;
    uint32_t soff[4];
    #pragma unroll
    for (int i = 0; i < 4; i++) soff[i] = sw128((uint32_t)am * 128 + (aq + i) * 16);

    {   // prologue: chunk 0 -> stage 0
        uint32_t tb = T0;
        #pragma unroll
        for (int i = 0; i < 4; i++) {
            float4 v = *(const float4*)(asrc + i * 4);
            hilo_sts(tb + soff[i], tb + TC_OFF_AL + soff[i], v);
            float4 w = *(const float4*)(bsrc + i * 4);
            hilo_sts(tb + TC_OFF_BH + soff[i], tb + TC_OFF_BL + soff[i], w);
        }
    }
    fence_proxy_async_cta();
    __syncthreads();

    uint32_t ph0 = 0, ph1 = 0;
    for (int c = 0; c < nch; c++) {
        int st = c & 1;
        if (wid == 0) {
            tc_fence_after();
            if (elect_one()) {
                uint32_t tb = T0 + st * TC_STAGE;
                uint64_t ah = mkdesc(tb), al = mkdesc(tb + TC_OFF_AL);
                uint64_t bh = mkdesc(tb + TC_OFF_BH), bl = mkdesc(tb + TC_OFF_BL);
                bool acc = (c > 0);
                #pragma unroll
                for (int j = 0; j < 4; j++) {
                    tc_mma_tf32(tmem, ah + j * 2, bh + j * 2, IDESC_TF32, acc); acc = true;
                    tc_mma_tf32(tmem, al + j * 2, bh + j * 2, IDESC_TF32, true);
                    tc_mma_tf32(tmem, ah + j * 2, bl + j * 2, IDESC_TF32, true);
                }
                tc_commit(st ? MB1 : MB0);
            }
        }
        if (c + 1 < nch) {
            if (c >= 1) {
                if (st == 0) { mbar_wait(MB1, ph1); ph1 ^= 1; }
                else         { mbar_wait(MB0, ph0); ph0 ^= 1; }
            }
            uint32_t tb = T0 + (st ^ 1) * TC_STAGE;
            int k0 = (c + 1) * 32;
            #pragma unroll
            for (int i = 0; i < 4; i++) {
                float4 v = *(const float4*)(asrc + k0 + i * 4);
                hilo_sts(tb + soff[i], tb + TC_OFF_AL + soff[i], v);
                float4 w = *(const float4*)(bsrc + k0 + i * 4);
                hilo_sts(tb + TC_OFF_BH + soff[i], tb + TC_OFF_BL + soff[i], w);
            }
            fence_proxy_async_cta();
        }
        __syncthreads();
    }

    if (((nch - 1) & 1) == 0) mbar_wait(MB0, ph0);
    else                      mbar_wait(MB1, ph1);
    tc_fence_after();

    {   // epilogue: warp w -> rows 32*(w&3)+lane, col half 64*(w>>2)
        int w = tid >> 5, l = tid & 31;
        int rl   = (w & 3) * 32 + l;
        int coff = (w >> 2) * 64;
        size_t grow = (size_t)(m0 + rl);
        #pragma unroll
        for (int cb = 0; cb < 64; cb += 32) {
            uint32_t r[32];
            LDTM_X32(r, tmem + coff + cb);
            tc_wait_ld();
            int gc = n0 + coff + cb;
            float* cp = C + grow * ldc + gc;
            #pragma unroll
            for (int j = 0; j < 8; j++) {
                float4 v = make_float4(__uint_as_float(r[4 * j + 0]),
                                       __uint_as_float(r[4 * j + 1]),
                                       __uint_as_float(r[4 * j + 2]),
                                       __uint_as_float(r[4 * j + 3]));
                if (EPI == 1) {
                    v.x = gelu_tanh(v.x + bias[gc + 4 * j + 0]);
                    v.y = gelu_tanh(v.y + bias[gc + 4 * j + 1]);
                    v.z = gelu_tanh(v.z + bias[gc + 4 * j + 2]);
                    v.w = gelu_tanh(v.w + bias[gc + 4 * j + 3]);
                } else if (EPI == 2) {
                    float4 rr = *(const float4*)(res + grow * ldc + gc + 4 * j);
                    v.x += rr.x; v.y += rr.y; v.z += rr.z; v.w += rr.w;
                } else if (EPI == 3) {
                    float4 o = *(const float4*)(cp + 4 * j);
                    v.x = o.x + v.x + bias[gc + 4 * j + 0];
                    v.y = o.y + v.y + bias[gc + 4 * j + 1];
                    v.z = o.z + v.z + bias[gc + 4 * j + 2];
                    v.w = o.w + v.w + bias[gc + 4 * j + 3];
                }
                *(float4*)(cp + 4 * j) = v;
            }
        }
        tc_fence_before();
    }
    __syncthreads();
    if (wid == 0) { tc_relinq(); tc_dealloc(tmem, 128); }

#else
    // ==================  mma.sync fallback path (sm_103)  ==================
    // 4-stage cp.async pipeline, K-chunk = 16, stride-20 smem padding.
    const int NST = 4;
    const int STB = 20480;                 // bytes per stage (A 10240 + B 10240)
    int nch = kEnd >> 4;
    uint32_t sbase = smem_u32(smem) + 1024;

    int lane = tid & 31;
    int wid  = tid >> 5;
    int wm   = wid & 1;                    // 2 warp rows (64 M each)
    int wn   = wid >> 1;                   // 4 warp cols (32 N each)
    int g    = lane >> 2;
    int t4   = lane & 3;

    // stage-load mapping: 2 A-chunks + 2 B-chunks of 16B per thread
    int r0 = tid >> 2, c0 = tid & 3;            // rows 0..63
    int r1 = (tid + 256) >> 2, c1 = tid & 3;    // rows 64..127

    float acc[4][4][4];
    #pragma unroll
    for (int a = 0; a < 4; a++)
        #pragma unroll
        for (int b = 0; b < 4; b++)
            #pragma unroll
            for (int q = 0; q < 4; q++) acc[a][b][q] = 0.f;

    // prologue: fill NST-1 stages
    #pragma unroll
    for (int s = 0; s < NST - 1; s++) {
        if (s < nch) {
            int k0 = s * 16;
            uint32_t st = sbase + s * STB;
            cpa16(st + r0 * 80 + c0 * 16,         A + (size_t)(m0 + r0) * K + k0 + c0 * 4);
            cpa16(st + r1 * 80 + c1 * 16,         A + (size_t)(m0 + r1) * K + k0 + c1 * 4);
            cpa16(st + 10240 + r0 * 80 + c0 * 16, B + (size_t)(n0 + r0) * K + k0 + c0 * 4);
            cpa16(st + 10240 + r1 * 80 + c1 * 16, B + (size_t)(n0 + r1) * K + k0 + c1 * 4);
        }
        cpa_commit();
    }

    for (int c = 0; c < nch; c++) {
        cpa_wait<NST - 2>();
        __syncthreads();
        int st = c & (NST - 1);
        const float* As = (const float*)(smem + 1024 + st * STB);
        const float* Bs = (const float*)(smem + 1024 + st * STB + 10240);

        #pragma unroll
        for (int kk = 0; kk < 16; kk += 8) {
            uint32_t ah[4][4], al[4][4], bh[4][2], bl[4][2];
            #pragma unroll
            for (int mi = 0; mi < 4; mi++) {
                const float* p = As + (wm * 64 + mi * 16 + g) * 20 + kk + t4;
                split_tf32(p[0],   ah[mi][0], al[mi][0]);   // a0 (r, k)
                split_tf32(p[160], ah[mi][1], al[mi][1]);   // a1 (r+8, k)
                split_tf32(p[4],   ah[mi][2], al[mi][2]);   // a2 (r, k+4)
                split_tf32(p[164], ah[mi][3], al[mi][3]);   // a3 (r+8, k+4)
            }
            #pragma unroll
            for (int ni = 0; ni < 4; ni++) {
                const float* p = Bs + (wn * 32 + ni * 8 + g) * 20 + kk + t4;
                split_tf32(p[0], bh[ni][0], bl[ni][0]);     // b0 (k, n)
                split_tf32(p[4], bh[ni][1], bl[ni][1]);     // b1 (k+4, n)
            }
            #pragma unroll
            for (int mi = 0; mi < 4; mi++)
                #pragma unroll
                for (int ni = 0; ni < 4; ni++) {
                    MMA_TF32(acc[mi][ni], ah[mi][0], ah[mi][1], ah[mi][2], ah[mi][3],
                             bh[ni][0], bh[ni][1]);
                    MMA_TF32(acc[mi][ni], al[mi][0], al[mi][1], al[mi][2], al[mi][3],
                             bh[ni][0], bh[ni][1]);
                    MMA_TF32(acc[mi][ni], ah[mi][0], ah[mi][1], ah[mi][2], ah[mi][3],
                             bl[ni][0], bl[ni][1]);
                }
        }
        __syncthreads();

        int nx = c + NST - 1;
        if (nx < nch) {
            int k0 = nx * 16;
            uint32_t stn = sbase + (nx & (NST - 1)) * STB;
            cpa16(stn + r0 * 80 + c0 * 16,         A + (size_t)(m0 + r0) * K + k0 + c0 * 4);
            cpa16(stn + r1 * 80 + c1 * 16,         A + (size_t)(m0 + r1) * K + k0 + c1 * 4);
            cpa16(stn + 10240 + r0 * 80 + c0 * 16, B + (size_t)(n0 + r0) * K + k0 + c0 * 4);
            cpa16(stn + 10240 + r1 * 80 + c1 * 16, B + (size_t)(n0 + r1) * K + k0 + c1 * 4);
        }
        cpa_commit();
    }
    cpa_wait<0>();

    // epilogue
    #pragma unroll
    for (int mi = 0; mi < 4; mi++) {
        #pragma unroll
        for (int ni = 0; ni < 4; ni++) {
            int gc = n0 + wn * 32 + ni * 8 + t4 * 2;
            #pragma unroll
            for (int hh = 0; hh < 2; hh++) {
                int grow = m0 + wm * 64 + mi * 16 + g + 8 * hh;
                float d0 = acc[mi][ni][2 * hh + 0];
                float d1 = acc[mi][ni][2 * hh + 1];
                size_t off = (size_t)grow * ldc + gc;
                if (EPI == 1) {
                    d0 = gelu_tanh(d0 + bias[gc + 0]);
                    d1 = gelu_tanh(d1 + bias[gc + 1]);
                } else if (EPI == 2) {
                    float2 rr = *(const float2*)(res + off);
                    d0 += rr.x; d1 += rr.y;
                } else if (EPI == 3) {
                    float2 o = *(const float2*)(C + off);
                    d0 = o.x + d0 + bias[gc + 0];
                    d1 = o.y + d1 + bias[gc + 1];
                }
                *(float2*)(C + off) = make_float2(d0, d1);
            }
        }
    }
#endif
}

// ---------------------------------------------------------------------------
// Host launcher
// ---------------------------------------------------------------------------
extern "C" void kernel_launch(void* const* d_in, const int* in_sizes, int n_in,
                              void* d_out, int out_size) {
    (void)in_sizes; (void)n_in; (void)out_size;
    const float* hidden   = (const float*)d_in[0];
    const float* ln_g     = (const float*)d_in[1];
    const float* ln_b     = (const float*)d_in[2];
    const float* wq       = (const float*)d_in[3];
    const float* wk       = (const float*)d_in[4];
    const float* wv       = (const float*)d_in[5];
    const float* wo       = (const float*)d_in[6];
    const float* fc_in_w  = (const float*)d_in[7];
    const float* fc_in_b  = (const float*)d_in[8];
    const float* fc_out_w = (const float*)d_in[9];
    const float* fc_out_b = (const float*)d_in[10];
    const float* past_k   = (const float*)d_in[11];
    const float* past_v   = (const float*)d_in[12];
    const int*   kloc     = (const int*)d_in[13];
    const int*   vloc     = (const int*)d_in[14];
    const int*   pos      = (const int*)d_in[15];
    float* out = (float*)d_out;

    float *h, *qlin, *klin, *vlin, *q, *kc, *vcT, *scores, *ctx, *act;
    float *wqT, *wkT, *wvT, *woT, *fiT, *foT;
    cudaGetSymbolAddress((void**)&h,      g_h);
    cudaGetSymbolAddress((void**)&qlin,   g_qlin);
    cudaGetSymbolAddress((void**)&klin,   g_klin);
    cudaGetSymbolAddress((void**)&vlin,   g_vlin);
    cudaGetSymbolAddress((void**)&q,      g_q);
    cudaGetSymbolAddress((void**)&kc,     g_kc);
    cudaGetSymbolAddress((void**)&vcT,    g_vcT);
    cudaGetSymbolAddress((void**)&scores, g_scores);
    cudaGetSymbolAddress((void**)&ctx,    g_ctx);
    cudaGetSymbolAddress((void**)&act,    g_act);
    cudaGetSymbolAddress((void**)&wqT,    g_wqT);
    cudaGetSymbolAddress((void**)&wkT,    g_wkT);
    cudaGetSymbolAddress((void**)&wvT,    g_wvT);
    cudaGetSymbolAddress((void**)&woT,    g_woT);
    cudaGetSymbolAddress((void**)&fiT,    g_fiT);
    cudaGetSymbolAddress((void**)&foT,    g_foT);

    cudaFuncSetAttribute(tc_gemm<0,false,false>, cudaFuncAttributeMaxDynamicSharedMemorySize, SMEMB);
    cudaFuncSetAttribute(tc_gemm<0,true ,false>, cudaFuncAttributeMaxDynamicSharedMemorySize, SMEMB);
    cudaFuncSetAttribute(tc_gemm<0,false,true >, cudaFuncAttributeMaxDynamicSharedMemorySize, SMEMB);
    cudaFuncSetAttribute(tc_gemm<1,false,false>, cudaFuncAttributeMaxDynamicSharedMemorySize, SMEMB);
    cudaFuncSetAttribute(tc_gemm<2,false,false>, cudaFuncAttributeMaxDynamicSharedMemorySize, SMEMB);
    cudaFuncSetAttribute(tc_gemm<3,false,false>, cudaFuncAttributeMaxDynamicSharedMemorySize, SMEMB);

    // 0) weight transposes (K-major B operands)
    dim3 tb(32, 8);
    transpose_kernel<<<dim3(E_/32,     E_/32),     tb>>>(wq,       wqT, E_,     E_);
    transpose_kernel<<<dim3(E_/32,     E_/32),     tb>>>(wk,       wkT, E_,     E_);
    transpose_kernel<<<dim3(E_/32,     E_/32),     tb>>>(wv,       wvT, E_,     E_);
    transpose_kernel<<<dim3(E_/32,     E_/32),     tb>>>(wo,       woT, E_,     E_);
    transpose_kernel<<<dim3(INNER_/32, E_/32),     tb>>>(fc_in_w,  fiT, E_,     INNER_);
    transpose_kernel<<<dim3(E_/32,     INNER_/32), tb>>>(fc_out_w, foT, INNER_, E_);

    // 1) LayerNorm
    ln_kernel<<<TOK_, 256>>>(hidden, ln_g, ln_b, h);

    // 2) QKV projections
    dim3 gq(E_ / 128, TOK_ / 128, 1);
    tc_gemm<0,false,false><<<gq, 256, SMEMB>>>(h, wqT, qlin, E_, E_, 0, 0, 0, 0, 1, nullptr, nullptr);
    tc_gemm<0,false,false><<<gq, 256, SMEMB>>>(h, wkT, klin, E_, E_, 0, 0, 0, 0, 1, nullptr, nullptr);
    tc_gemm<0,false,false><<<gq, 256, SMEMB>>>(h, wvT, vlin, E_, E_, 0, 0, 0, 0, 1, nullptr, nullptr);

    // 3) caches + RoPE
    {
        size_t total = (size_t)B_ * S_ * H_ * D_;
        cache_init_kernel<<<(unsigned)((total + 255) / 256), 256>>>(past_k, past_v, kc, vcT);
    }
    rope_scatter_kernel<<<B_ * S_ * H_, 128>>>(qlin, klin, vlin, kloc, vloc, pos, q, kc, vcT);

    // 4) scores = q @ k^T (batched, causal block skip)
    dim3 gs(S_ / 128, S_ / 128, BH_);
    tc_gemm<0,true,false><<<gs, 256, SMEMB>>>(
        q, kc, scores, D_, S_,
        (long long)S_ * D_, (long long)S_ * D_,
        (long long)S_ * S_, 0, 1, nullptr, nullptr);

    // 5) softmax (causal)
    softmax_kernel<<<BH_ * S_, 256>>>(scores);

    // 6) ctx = probs @ V (batched, K clamped causally), writes (B,S,E)
    dim3 gav(D_ / 128, S_ / 128, BH_);
    tc_gemm<0,false,true><<<gav, 256, SMEMB>>>(
        scores, vcT, ctx, S_, E_,
        (long long)S_ * S_, (long long)D_ * S_,
        (long long)S_ * E_, (long long)D_, H_, nullptr, nullptr);

    // 7) out = ctx @ wo + hidden
    tc_gemm<2,false,false><<<gq, 256, SMEMB>>>(ctx, woT, out, E_, E_, 0, 0, 0, 0, 1, nullptr, hidden);

    // 8) act = gelu(h @ fc_in + b)
    dim3 gfi(INNER_ / 128, TOK_ / 128, 1);
    tc_gemm<1,false,false><<<gfi, 256, SMEMB>>>(h, fiT, act, E_, INNER_, 0, 0, 0, 0, 1, fc_in_b, nullptr);

    // 9) out += act @ fc_out + b
    tc_gemm<3,false,false><<<gq, 256, SMEMB>>>(act, foT, out, INNER_, E_, 0, 0, 0, 0, 1, fc_out_b, nullptr);
}